// round 16
// baseline (speedup 1.0000x reference)
#include <cuda_runtime.h>
#include <cuda_bf16.h>
#include <math.h>
#include <stdint.h>

#define S_LEN 2048
#define D_MODEL 2048
#define NH 32
#define NKV 8
#define HD 64
#define KV_DIM (NKV * HD)   // 512

// Scratch (no allocations allowed)
__device__ float g_q[S_LEN * D_MODEL];
__device__ float g_k[S_LEN * KV_DIM];
__device__ float g_v[S_LEN * KV_DIM];
// Pre-split bf16-pair (u32 = [odd|even]) operand arrays
__device__ unsigned g_xH[S_LEN * D_MODEL / 2],  g_xL[S_LEN * D_MODEL / 2];
__device__ unsigned g_aH[S_LEN * D_MODEL / 2],  g_aL[S_LEN * D_MODEL / 2];
__device__ unsigned g_wqH[D_MODEL * D_MODEL / 2], g_wqL[D_MODEL * D_MODEL / 2];
__device__ unsigned g_wkH[KV_DIM * D_MODEL / 2],  g_wkL[KV_DIM * D_MODEL / 2];
__device__ unsigned g_wvH[KV_DIM * D_MODEL / 2],  g_wvL[KV_DIM * D_MODEL / 2];
__device__ unsigned g_woH[D_MODEL * D_MODEL / 2], g_woL[D_MODEL * D_MODEL / 2];
// Pre-split attention operands: K [kv][s][d/2], V-transposed [kv][d][s/2]
__device__ unsigned g_kHs[NKV * S_LEN * HD / 2], g_kLs[NKV * S_LEN * HD / 2];
__device__ unsigned g_vtH[NKV * HD * S_LEN / 2], g_vtL[NKV * HD * S_LEN / 2];

// ---------------------------------------------------------------------------
__device__ __forceinline__ void split2(float x0, float x1, unsigned& hi, unsigned& lo)
{
    __nv_bfloat162 h = __floats2bfloat162_rn(x0, x1);
    float h0 = __low2float(h), h1 = __high2float(h);
    __nv_bfloat162 l = __floats2bfloat162_rn(x0 - h0, x1 - h1);
    hi = *reinterpret_cast<unsigned*>(&h);
    lo = *reinterpret_cast<unsigned*>(&l);
}

__device__ __forceinline__ void mma_bf16(float* c, unsigned a0, unsigned a1,
                                         unsigned a2, unsigned a3,
                                         unsigned b0, unsigned b1)
{
    asm volatile(
        "mma.sync.aligned.m16n8k16.row.col.f32.bf16.bf16.f32 "
        "{%0,%1,%2,%3},{%4,%5,%6,%7},{%8,%9},{%0,%1,%2,%3};\n"
        : "+f"(c[0]), "+f"(c[1]), "+f"(c[2]), "+f"(c[3])
        : "r"(a0), "r"(a1), "r"(a2), "r"(a3), "r"(b0), "r"(b1));
}

__device__ __forceinline__ uint32_t smem_u32(const void* p)
{
    uint32_t a;
    asm("{ .reg .u64 t; cvta.to.shared.u64 t, %1; cvt.u32.u64 %0, t; }"
        : "=r"(a) : "l"(p));
    return a;
}

__device__ __forceinline__ void ldsm4(unsigned& r0, unsigned& r1,
                                      unsigned& r2, unsigned& r3, uint32_t addr)
{
    asm volatile("ldmatrix.sync.aligned.m8n8.x4.shared.b16 {%0,%1,%2,%3}, [%4];"
                 : "=r"(r0), "=r"(r1), "=r"(r2), "=r"(r3) : "r"(addr));
}

__device__ __forceinline__ void cpa16(uint32_t dst, const unsigned* src)
{
    asm volatile("cp.async.cg.shared.global [%0], [%1], 16;"
                 :: "r"(dst), "l"(src) : "memory");
}
#define CP_COMMIT() asm volatile("cp.async.commit_group;" ::: "memory")
#define CP_WAIT(n)  asm volatile("cp.async.wait_group %0;" :: "n"(n) : "memory")

// ---------------------------------------------------------------------------
// Pre-split kernels
// ---------------------------------------------------------------------------
__global__ void split_rows_kernel(const float* __restrict__ X,
                                  unsigned* __restrict__ H, unsigned* __restrict__ L,
                                  int total_pairs)
{
    int i = blockIdx.x * blockDim.x + threadIdx.x;
    if (i >= total_pairs) return;
    float2 v = reinterpret_cast<const float2*>(X)[i];
    unsigned hh, ll;
    split2(v.x, v.y, hh, ll);
    H[i] = hh;  L[i] = ll;
}

// W[K][N] fp32 -> H/L [N][K/2] bf16-pair u32 (transposed)
__global__ void splitT_kernel(const float* __restrict__ W,
                              unsigned* __restrict__ H, unsigned* __restrict__ L,
                              int K, int N)
{
    __shared__ float tile[32][33];
    const int kt = blockIdx.x * 32, nt = blockIdx.y * 32;
    const int t = threadIdx.x;
    const int kl = t >> 5, nl = t & 31;
#pragma unroll
    for (int j = 0; j < 4; j++)
        tile[kl + 8 * j][nl] = W[(size_t)(kt + kl + 8 * j) * N + nt + nl];
    __syncthreads();
    const int n = t >> 3, p0 = t & 7;
#pragma unroll
    for (int j = 0; j < 2; j++) {
        int p = p0 + 8 * j;
        unsigned hh, ll;
        split2(tile[2 * p][n], tile[2 * p + 1][n], hh, ll);
        size_t o = (size_t)(nt + n) * (K / 2) + kt / 2 + p;
        H[o] = hh;  L[o] = ll;
    }
}

// g_k [s][kv*64+d] (post-RoPE) -> g_kHs/g_kLs [kv][s][32]
__global__ void split_k_kernel()
{
    int i = blockIdx.x * blockDim.x + threadIdx.x;
    const int total = NKV * S_LEN * 32;
    if (i >= total) return;
    int p = i & 31;
    int s = (i >> 5) & (S_LEN - 1);
    int kv = i >> (5 + 11);
    const float* src = g_k + (size_t)s * KV_DIM + kv * HD + 2 * p;
    unsigned hh, ll;
    split2(src[0], src[1], hh, ll);
    g_kHs[i] = hh;  g_kLs[i] = ll;
}

// g_v [s][kv*64+d] -> g_vtH/g_vtL [kv][d][s/2]  (smem transpose, 64s x 64d tiles)
__global__ void split_vt_kernel()
{
    __shared__ float tile[64][65];
    const int kv = blockIdx.x, sb = blockIdx.y * 64;
    const int t = threadIdx.x;
    // load: 64 rows x 16 float4 = 1024 float4; thread does 4
    const int lr = t >> 4, ld4 = t & 15;
#pragma unroll
    for (int j = 0; j < 4; j++) {
        int r = lr + 16 * j;
        float4 v = *reinterpret_cast<const float4*>(
            &g_v[(size_t)(sb + r) * KV_DIM + kv * HD + ld4 * 4]);
        tile[r][ld4 * 4 + 0] = v.x;  tile[r][ld4 * 4 + 1] = v.y;
        tile[r][ld4 * 4 + 2] = v.z;  tile[r][ld4 * 4 + 3] = v.w;
    }
    __syncthreads();
    // write: 64 d x 32 spairs = 2048; thread does 8
#pragma unroll
    for (int j = 0; j < 8; j++) {
        int idx = t + 256 * j;
        int d = idx >> 5, sp = idx & 31;
        unsigned hh, ll;
        split2(tile[2 * sp][d], tile[2 * sp + 1][d], hh, ll);
        size_t o = (size_t)kv * (HD * S_LEN / 2) + (size_t)d * (S_LEN / 2) + sb / 2 + sp;
        g_vtH[o] = hh;  g_vtL[o] = ll;
    }
}

// ---------------------------------------------------------------------------
// cp.async double-buffered 3xBF16 GEMM (unchanged from R15).
// ---------------------------------------------------------------------------
#define GST 20
#define ST_U32 (128 * GST)
#define STAGE_BYTES (4 * ST_U32 * 4)
#define GEMM_SMEM (2 * STAGE_BYTES)

__device__ __forceinline__ void gemm_body(
    const unsigned* __restrict__ AH, const unsigned* __restrict__ AL,
    const unsigned* __restrict__ BH, const unsigned* __restrict__ BL,
    float* __restrict__ C, int N, int K, int bx, int by)
{
    extern __shared__ unsigned smg[];
    const int tid = threadIdx.x;
    const int lane = tid & 31, wid = tid >> 5;
    const int wm = wid & 1, wn = wid >> 1;
    const int g = lane >> 2, q = lane & 3;
    const uint32_t sb = smem_u32(smg);

    const int KP = K >> 1;
    AH += (size_t)(by * 128) * KP;  AL += (size_t)(by * 128) * KP;
    BH += (size_t)(bx * 128) * KP;  BL += (size_t)(bx * 128) * KP;
    C += (size_t)by * 128 * N + (size_t)bx * 128;

    const int sRow = tid >> 1, sC = (tid & 1) * 2;
    const uint32_t dstRow = sb + sRow * GST * 4 + sC * 16;
    const size_t srcRow = (size_t)sRow * KP + sC * 4;

    const int sel = lane >> 3, rin = lane & 7;
    uint32_t aOff[4];
#pragma unroll
    for (int mt = 0; mt < 4; mt++)
        aOff[mt] = (uint32_t)((wm * 64 + mt * 16 + (sel & 1) * 8 + rin) * GST * 4
                              + (sel >> 1) * 16);
    uint32_t bOff[2];
#pragma unroll
    for (int np = 0; np < 2; np++)
        bOff[np] = (uint32_t)((wn * 32 + np * 16 + (sel >> 1) * 8 + rin) * GST * 4
                              + (sel & 1) * 16);

    float c[4][4][4];
#pragma unroll
    for (int mt = 0; mt < 4; mt++)
#pragma unroll
        for (int nt = 0; nt < 4; nt++)
#pragma unroll
            for (int i = 0; i < 4; i++) c[mt][nt][i] = 0.f;

    const int NT = K / 32;

#define ISSUE_STAGE(buf, tile_)                                                  \
    do {                                                                         \
        uint32_t d0 = dstRow + (buf) * STAGE_BYTES;                              \
        size_t s0 = srcRow + (size_t)(tile_) * 16;                               \
        cpa16(d0,                     AH + s0);  cpa16(d0 + 16,                  AH + s0 + 4); \
        cpa16(d0 + ST_U32 * 4,        AL + s0);  cpa16(d0 + 16 + ST_U32 * 4,     AL + s0 + 4); \
        cpa16(d0 + 2 * ST_U32 * 4,    BH + s0);  cpa16(d0 + 16 + 2 * ST_U32 * 4, BH + s0 + 4); \
        cpa16(d0 + 3 * ST_U32 * 4,    BL + s0);  cpa16(d0 + 16 + 3 * ST_U32 * 4, BL + s0 + 4); \
    } while (0)

    ISSUE_STAGE(0, 0);
    CP_COMMIT();

    for (int t = 0; t < NT; t++) {
        const int buf = t & 1;
        if (t + 1 < NT) {
            ISSUE_STAGE(buf ^ 1, t + 1);
            CP_COMMIT();
            CP_WAIT(1);
        } else {
            CP_WAIT(0);
        }
        __syncthreads();

        const uint32_t aHb = sb + buf * STAGE_BYTES;
        const uint32_t aLb = aHb + ST_U32 * 4;
        const uint32_t bHb = aHb + 2 * ST_U32 * 4;
        const uint32_t bLb = aHb + 3 * ST_U32 * 4;

#pragma unroll
        for (int c8 = 0; c8 < 2; c8++) {
            const uint32_t kB = c8 * 32;
            unsigned ah[4][4], al[4][4];
#pragma unroll
            for (int mt = 0; mt < 4; mt++) {
                ldsm4(ah[mt][0], ah[mt][1], ah[mt][2], ah[mt][3], aHb + aOff[mt] + kB);
                ldsm4(al[mt][0], al[mt][1], al[mt][2], al[mt][3], aLb + aOff[mt] + kB);
            }
#pragma unroll
            for (int np = 0; np < 2; np++) {
                unsigned bh[4], bl[4];
                ldsm4(bh[0], bh[1], bh[2], bh[3], bHb + bOff[np] + kB);
                ldsm4(bl[0], bl[1], bl[2], bl[3], bLb + bOff[np] + kB);
#pragma unroll
                for (int sub = 0; sub < 2; sub++) {
                    int nt = np * 2 + sub;
#pragma unroll
                    for (int mt = 0; mt < 4; mt++) {
                        mma_bf16(c[mt][nt], ah[mt][0], ah[mt][1], ah[mt][2], ah[mt][3],
                                 bh[sub * 2], bh[sub * 2 + 1]);
                        mma_bf16(c[mt][nt], al[mt][0], al[mt][1], al[mt][2], al[mt][3],
                                 bh[sub * 2], bh[sub * 2 + 1]);
                        mma_bf16(c[mt][nt], ah[mt][0], ah[mt][1], ah[mt][2], ah[mt][3],
                                 bl[sub * 2], bl[sub * 2 + 1]);
                    }
                }
            }
        }
        __syncthreads();
    }
#undef ISSUE_STAGE

#pragma unroll
    for (int mt = 0; mt < 4; mt++) {
#pragma unroll
        for (int nt = 0; nt < 4; nt++) {
            int row = wm * 64 + mt * 16 + g;
            int col = wn * 32 + nt * 8 + q * 2;
            *reinterpret_cast<float2*>(&C[(size_t)row * N + col]) =
                make_float2(c[mt][nt][0], c[mt][nt][1]);
            *reinterpret_cast<float2*>(&C[(size_t)(row + 8) * N + col]) =
                make_float2(c[mt][nt][2], c[mt][nt][3]);
        }
    }
}

__global__ __launch_bounds__(256, 2) void qkv_gemm_kernel(
    const unsigned* __restrict__ xH, const unsigned* __restrict__ xL)
{
    int bx = blockIdx.x;
    const unsigned *BH, *BL; float* C; int N; int cx;
    if (bx < 16)      { BH = g_wqH; BL = g_wqL; C = g_q; N = D_MODEL; cx = bx; }
    else if (bx < 20) { BH = g_wkH; BL = g_wkL; C = g_k; N = KV_DIM;  cx = bx - 16; }
    else              { BH = g_wvH; BL = g_wvL; C = g_v; N = KV_DIM;  cx = bx - 20; }
    gemm_body(xH, xL, BH, BL, C, N, D_MODEL, cx, blockIdx.y);
}

__global__ __launch_bounds__(256, 2) void out_gemm_kernel(float* __restrict__ C)
{
    gemm_body(g_aH, g_aL, g_woH, g_woL, C, D_MODEL, D_MODEL, blockIdx.x, blockIdx.y);
}

// ---------------------------------------------------------------------------
// RoPE in place on g_q, g_k.
// ---------------------------------------------------------------------------
__global__ void rope_kernel(const float* __restrict__ cosT, const float* __restrict__ sinT)
{
    int idx = blockIdx.x * blockDim.x + threadIdx.x;
    const int total = S_LEN * (NH + NKV) * (HD / 2);
    if (idx >= total) return;
    int d = idx & 31;
    int row = idx >> 5;
    float* p;
    int s;
    if (row < S_LEN * NH) {
        s = row >> 5;
        int h = row & 31;
        p = g_q + (size_t)s * D_MODEL + h * HD;
    } else {
        int r = row - S_LEN * NH;
        s = r >> 3;
        int kv = r & 7;
        p = g_k + (size_t)s * KV_DIM + kv * HD;
    }
    float c = cosT[s * HD + d];
    float sn = sinT[s * HD + d];
    float x1 = p[d];
    float x2 = p[d + 32];
    p[d]      = x1 * c - x2 * sn;
    p[d + 32] = x1 * sn + x2 * c;
}

// ---------------------------------------------------------------------------
// Tensor-core causal GQA attention. K/V pre-split in gmem; staging is pure
// cp.async, double-buffered across kt. Reverse-qb scheduling (long CTAs first).
// Smem: 2 stages x {KsH,KsL,VtH,VtL} x [64][AST] u32 = 73728 B.
// ---------------------------------------------------------------------------
#define AST 36
#define A_ARR (64 * AST)                 // u32 per array
#define A_STAGEB (4 * A_ARR * 4)         // 36864 B per stage
#define ATTN_SMEM (2 * A_STAGEB)         // 73728 B

__global__ __launch_bounds__(128, 3) void attn_tc_kernel()
{
    extern __shared__ unsigned smA[];
    const int qb = (S_LEN / 64 - 1) - blockIdx.x;   // long CTAs first
    const int h = blockIdx.y, kvh = h >> 2;
    const int t = threadIdx.x;
    const int lane = t & 31, w = t >> 5;
    const int g = lane >> 2, q = lane & 3;
    const int r0 = w * 16 + g;
    const uint32_t sb = smem_u32(smA);

    const unsigned* kHp = g_kHs + (size_t)kvh * (S_LEN * 32);
    const unsigned* kLp = g_kLs + (size_t)kvh * (S_LEN * 32);
    const unsigned* vHp = g_vtH + (size_t)kvh * (HD * S_LEN / 2);
    const unsigned* vLp = g_vtL + (size_t)kvh * (HD * S_LEN / 2);

    const int sel = lane >> 3, rin = lane & 7;
    uint32_t nOff[4];
#pragma unroll
    for (int np = 0; np < 4; np++)
        nOff[np] = (uint32_t)((np * 16 + (sel >> 1) * 8 + rin) * AST * 4
                              + (sel & 1) * 16);

    // ---- stage Q (scaled, split) into stage-1 KsH/KsL ----
    unsigned* QH = smA + A_ARR * 4;         // stage1 KsH
    unsigned* QL = QH + A_ARR;              // stage1 KsL
#pragma unroll
    for (int j = 0; j < 8; j++) {
        int i = t + 128 * j;
        int r = i >> 4, d4 = i & 15;
        float4 v = *reinterpret_cast<const float4*>(
            &g_q[(size_t)(qb * 64 + r) * D_MODEL + h * HD + d4 * 4]);
        unsigned h0, l0, h1, l1;
        split2(v.x * 0.125f, v.y * 0.125f, h0, l0);
        split2(v.z * 0.125f, v.w * 0.125f, h1, l1);
        QH[r * AST + d4 * 2] = h0;      QL[r * AST + d4 * 2] = l0;
        QH[r * AST + d4 * 2 + 1] = h1;  QL[r * AST + d4 * 2 + 1] = l1;
    }
    __syncthreads();

    unsigned qh[4][4], ql[4][4];
#pragma unroll
    for (int c8 = 0; c8 < 4; c8++) {
        qh[c8][0] = QH[r0 * AST + c8 * 8 + q];
        qh[c8][1] = QH[(r0 + 8) * AST + c8 * 8 + q];
        qh[c8][2] = QH[r0 * AST + c8 * 8 + q + 4];
        qh[c8][3] = QH[(r0 + 8) * AST + c8 * 8 + q + 4];
        ql[c8][0] = QL[r0 * AST + c8 * 8 + q];
        ql[c8][1] = QL[(r0 + 8) * AST + c8 * 8 + q];
        ql[c8][2] = QL[r0 * AST + c8 * 8 + q + 4];
        ql[c8][3] = QL[(r0 + 8) * AST + c8 * 8 + q + 4];
    }
    __syncthreads();   // everyone done reading Q scratch before kt=1 prefetch lands

    // cp.async staging: thread -> row sr (0..63), 16B-chunk group (t&1)*4
    const int sr = t >> 1;
    const int hc = (t & 1) * 16;             // u32 offset within 32-u32 row: 0 or 16
    const uint32_t dRow = sb + sr * AST * 4 + hc * 4;

#define A_ISSUE(buf, kt_)                                                        \
    do {                                                                         \
        uint32_t d0 = dRow + (buf) * A_STAGEB;                                   \
        const unsigned* ks = kHp + (size_t)((kt_) * 64 + sr) * 32 + hc;          \
        const unsigned* ks2 = kLp + (size_t)((kt_) * 64 + sr) * 32 + hc;         \
        const unsigned* vs = vHp + (size_t)sr * (S_LEN / 2) + (kt_) * 32 + hc;   \
        const unsigned* vs2 = vLp + (size_t)sr * (S_LEN / 2) + (kt_) * 32 + hc;  \
        cpa16(d0,                ks);       cpa16(d0 + 16,                ks + 4);  \
        cpa16(d0 + 32,           ks + 8);   cpa16(d0 + 48,               ks + 12); \
        cpa16(d0 + A_ARR * 4,      ks2);     cpa16(d0 + A_ARR * 4 + 16,    ks2 + 4); \
        cpa16(d0 + A_ARR * 4 + 32, ks2 + 8); cpa16(d0 + A_ARR * 4 + 48,   ks2 + 12); \
        cpa16(d0 + 2 * A_ARR * 4,      vs);     cpa16(d0 + 2 * A_ARR * 4 + 16,  vs + 4); \
        cpa16(d0 + 2 * A_ARR * 4 + 32, vs + 8); cpa16(d0 + 2 * A_ARR * 4 + 48,  vs + 12); \
        cpa16(d0 + 3 * A_ARR * 4,      vs2);     cpa16(d0 + 3 * A_ARR * 4 + 16, vs2 + 4); \
        cpa16(d0 + 3 * A_ARR * 4 + 32, vs2 + 8); cpa16(d0 + 3 * A_ARR * 4 + 48, vs2 + 12); \
    } while (0)

    float m0 = -1e30f, m1 = -1e30f, l0s = 0.f, l1s = 0.f;
    float acc[8][4];
#pragma unroll
    for (int nt = 0; nt < 8; nt++)
#pragma unroll
        for (int i = 0; i < 4; i++) acc[nt][i] = 0.f;

    A_ISSUE(0, 0);
    CP_COMMIT();

    for (int kt = 0; kt <= qb; kt++) {
        const int buf = kt & 1;
        if (kt < qb) {
            A_ISSUE(buf ^ 1, kt + 1);
            CP_COMMIT();
            CP_WAIT(1);
        } else {
            CP_WAIT(0);
        }
        __syncthreads();

        const uint32_t kHb = sb + buf * A_STAGEB;
        const uint32_t kLb = kHb + A_ARR * 4;
        const uint32_t vHb = kHb + 2 * A_ARR * 4;
        const uint32_t vLb = kHb + 3 * A_ARR * 4;

        // ---- scores S = Q K^T (3xBF16) ----
        float c[8][4];
#pragma unroll
        for (int nt = 0; nt < 8; nt++)
#pragma unroll
            for (int i = 0; i < 4; i++) c[nt][i] = 0.f;

#pragma unroll
        for (int c8 = 0; c8 < 4; c8++) {
            const uint32_t kB = c8 * 32;
#pragma unroll
            for (int np = 0; np < 4; np++) {
                unsigned bh[4], bl[4];
                ldsm4(bh[0], bh[1], bh[2], bh[3], kHb + nOff[np] + kB);
                ldsm4(bl[0], bl[1], bl[2], bl[3], kLb + nOff[np] + kB);
#pragma unroll
                for (int sub = 0; sub < 2; sub++) {
                    int nt = np * 2 + sub;
                    mma_bf16(c[nt], qh[c8][0], qh[c8][1], qh[c8][2], qh[c8][3],
                             bh[sub * 2], bh[sub * 2 + 1]);
                    mma_bf16(c[nt], ql[c8][0], ql[c8][1], ql[c8][2], ql[c8][3],
                             bh[sub * 2], bh[sub * 2 + 1]);
                    mma_bf16(c[nt], qh[c8][0], qh[c8][1], qh[c8][2], qh[c8][3],
                             bl[sub * 2], bl[sub * 2 + 1]);
                }
            }
        }

        if (kt == qb) {
#pragma unroll
            for (int nt = 0; nt < 8; nt++) {
                int k0c = nt * 8 + 2 * q;
                if (k0c     > r0)     c[nt][0] = -1e30f;
                if (k0c + 1 > r0)     c[nt][1] = -1e30f;
                if (k0c     > r0 + 8) c[nt][2] = -1e30f;
                if (k0c + 1 > r0 + 8) c[nt][3] = -1e30f;
            }
        }

        float tm0 = -1e30f, tm1 = -1e30f;
#pragma unroll
        for (int nt = 0; nt < 8; nt++) {
            tm0 = fmaxf(tm0, fmaxf(c[nt][0], c[nt][1]));
            tm1 = fmaxf(tm1, fmaxf(c[nt][2], c[nt][3]));
        }
        tm0 = fmaxf(tm0, __shfl_xor_sync(0xffffffffu, tm0, 1));
        tm0 = fmaxf(tm0, __shfl_xor_sync(0xffffffffu, tm0, 2));
        tm1 = fmaxf(tm1, __shfl_xor_sync(0xffffffffu, tm1, 1));
        tm1 = fmaxf(tm1, __shfl_xor_sync(0xffffffffu, tm1, 2));
        float nm0 = fmaxf(m0, tm0), nm1 = fmaxf(m1, tm1);
        float es0 = __expf(m0 - nm0), es1 = __expf(m1 - nm1);

        float ps0 = 0.f, ps1 = 0.f;
#pragma unroll
        for (int nt = 0; nt < 8; nt++) {
            c[nt][0] = __expf(c[nt][0] - nm0);
            c[nt][1] = __expf(c[nt][1] - nm0);
            c[nt][2] = __expf(c[nt][2] - nm1);
            c[nt][3] = __expf(c[nt][3] - nm1);
            ps0 += c[nt][0] + c[nt][1];
            ps1 += c[nt][2] + c[nt][3];
        }
        ps0 += __shfl_xor_sync(0xffffffffu, ps0, 1);
        ps0 += __shfl_xor_sync(0xffffffffu, ps0, 2);
        ps1 += __shfl_xor_sync(0xffffffffu, ps1, 1);
        ps1 += __shfl_xor_sync(0xffffffffu, ps1, 2);
        l0s = l0s * es0 + ps0;
        l1s = l1s * es1 + ps1;
        m0 = nm0; m1 = nm1;

#pragma unroll
        for (int nt = 0; nt < 8; nt++) {
            acc[nt][0] *= es0; acc[nt][1] *= es0;
            acc[nt][2] *= es1; acc[nt][3] *= es1;
        }

        // P fragments directly from score registers
        unsigned ph[4][4], pl[4][4];
#pragma unroll
        for (int c8 = 0; c8 < 4; c8++) {
            split2(c[2 * c8][0],     c[2 * c8][1],     ph[c8][0], pl[c8][0]);
            split2(c[2 * c8][2],     c[2 * c8][3],     ph[c8][1], pl[c8][1]);
            split2(c[2 * c8 + 1][0], c[2 * c8 + 1][1], ph[c8][2], pl[c8][2]);
            split2(c[2 * c8 + 1][2], c[2 * c8 + 1][3], ph[c8][3], pl[c8][3]);
        }

        // ---- O += P V (3xBF16) ----
#pragma unroll
        for (int c8 = 0; c8 < 4; c8++) {
            const uint32_t kB = c8 * 32;
#pragma unroll
            for (int np = 0; np < 4; np++) {
                unsigned bh[4], bl[4];
                ldsm4(bh[0], bh[1], bh[2], bh[3], vHb + nOff[np] + kB);
                ldsm4(bl[0], bl[1], bl[2], bl[3], vLb + nOff[np] + kB);
#pragma unroll
                for (int sub = 0; sub < 2; sub++) {
                    int nt = np * 2 + sub;
                    mma_bf16(acc[nt], ph[c8][0], ph[c8][1], ph[c8][2], ph[c8][3],
                             bh[sub * 2], bh[sub * 2 + 1]);
                    mma_bf16(acc[nt], pl[c8][0], pl[c8][1], pl[c8][2], pl[c8][3],
                             bh[sub * 2], bh[sub * 2 + 1]);
                    mma_bf16(acc[nt], ph[c8][0], ph[c8][1], ph[c8][2], ph[c8][3],
                             bl[sub * 2], bl[sub * 2 + 1]);
                }
            }
        }
        __syncthreads();   // reads of buf done before it is refilled (kt+2)
    }
#undef A_ISSUE

    // ---- epilogue: write pre-split bf16 output for the out GEMM ----
    float inv0 = 1.f / l0s, inv1 = 1.f / l1s;
    const size_t rowU0 = ((size_t)(qb * 64 + r0) * D_MODEL + h * HD) >> 1;
    const size_t rowU1 = ((size_t)(qb * 64 + r0 + 8) * D_MODEL + h * HD) >> 1;
#pragma unroll
    for (int nt = 0; nt < 8; nt++) {
        unsigned hh, ll;
        split2(acc[nt][0] * inv0, acc[nt][1] * inv0, hh, ll);
        g_aH[rowU0 + nt * 4 + q] = hh;
        g_aL[rowU0 + nt * 4 + q] = ll;
        split2(acc[nt][2] * inv1, acc[nt][3] * inv1, hh, ll);
        g_aH[rowU1 + nt * 4 + q] = hh;
        g_aL[rowU1 + nt * 4 + q] = ll;
    }
}

// ---------------------------------------------------------------------------
extern "C" void kernel_launch(void* const* d_in, const int* in_sizes, int n_in,
                              void* d_out, int out_size)
{
    const float* x    = (const float*)d_in[0];
    const float* cosT = (const float*)d_in[1];
    const float* sinT = (const float*)d_in[2];
    // d_in[3] = mask: causal, applied analytically
    const float* wq = (const float*)d_in[4];
    const float* wk = (const float*)d_in[5];
    const float* wv = (const float*)d_in[6];
    const float* wo = (const float*)d_in[7];
    float* out = (float*)d_out;

    float *kp, *vp;
    unsigned *xH, *xL, *wqH, *wqL, *wkH, *wkL, *wvH, *wvL, *woH, *woL;
    cudaGetSymbolAddress((void**)&kp, g_k);
    cudaGetSymbolAddress((void**)&vp, g_v);
    cudaGetSymbolAddress((void**)&xH, g_xH);   cudaGetSymbolAddress((void**)&xL, g_xL);
    cudaGetSymbolAddress((void**)&wqH, g_wqH); cudaGetSymbolAddress((void**)&wqL, g_wqL);
    cudaGetSymbolAddress((void**)&wkH, g_wkH); cudaGetSymbolAddress((void**)&wkL, g_wkL);
    cudaGetSymbolAddress((void**)&wvH, g_wvH); cudaGetSymbolAddress((void**)&wvL, g_wvL);
    cudaGetSymbolAddress((void**)&woH, g_woH); cudaGetSymbolAddress((void**)&woL, g_woL);

    // Pre-split GEMM operands
    const int xPairs = S_LEN * D_MODEL / 2;
    split_rows_kernel<<<(xPairs + 255) / 256, 256>>>(x, xH, xL, xPairs);
    splitT_kernel<<<dim3(D_MODEL / 32, D_MODEL / 32), 256>>>(wq, wqH, wqL, D_MODEL, D_MODEL);
    splitT_kernel<<<dim3(D_MODEL / 32, KV_DIM / 32), 256>>>(wk, wkH, wkL, D_MODEL, KV_DIM);
    splitT_kernel<<<dim3(D_MODEL / 32, KV_DIM / 32), 256>>>(wv, wvH, wvL, D_MODEL, KV_DIM);
    splitT_kernel<<<dim3(D_MODEL / 32, D_MODEL / 32), 256>>>(wo, woH, woL, D_MODEL, D_MODEL);

    cudaFuncSetAttribute(qkv_gemm_kernel, cudaFuncAttributeMaxDynamicSharedMemorySize, GEMM_SMEM);
    cudaFuncSetAttribute(out_gemm_kernel, cudaFuncAttributeMaxDynamicSharedMemorySize, GEMM_SMEM);

    qkv_gemm_kernel<<<dim3(24, S_LEN / 128), 256, GEMM_SMEM>>>(xH, xL);

    const int ropeTot = S_LEN * (NH + NKV) * (HD / 2);
    rope_kernel<<<(ropeTot + 255) / 256, 256>>>(cosT, sinT);

    // Pre-split attention operands (K post-RoPE, V raw)
    split_k_kernel<<<(NKV * S_LEN * 32 + 255) / 256, 256>>>();
    split_vt_kernel<<<dim3(NKV, S_LEN / 64), 256>>>();

    cudaFuncSetAttribute(attn_tc_kernel, cudaFuncAttributeMaxDynamicSharedMemorySize, ATTN_SMEM);
    attn_tc_kernel<<<dim3(S_LEN / 64, NH), 128, ATTN_SMEM>>>();

    out_gemm_kernel<<<dim3(D_MODEL / 128, S_LEN / 128), 256, GEMM_SMEM>>>(out);

    const size_t outElems = (size_t)S_LEN * D_MODEL;
    const size_t kvElems = (size_t)S_LEN * KV_DIM;
    if ((size_t)out_size >= outElems + 2 * kvElems) {
        cudaMemcpyAsync(out + outElems, kp, kvElems * sizeof(float),
                        cudaMemcpyDeviceToDevice);
        cudaMemcpyAsync(out + outElems + kvElems, vp, kvElems * sizeof(float),
                        cudaMemcpyDeviceToDevice);
    }
}